// round 15
// baseline (speedup 1.0000x reference)
#include <cuda_runtime.h>

#define BN 8
#define JN 64
#define CN 32
#define HT 8
#define HIMG_ 256
#define WIMG_ 256
#define HW (HIMG_*WIMG_)
#define NXMAX 216          // max x-range of a box: bw<=200 -> nx<=204

// One block per (box, output row i). Phase 1: blend the two source image rows
// into smem G[c][x] = wy1*img[c][y0][x] + wy0*img[c][y1][x] (coalesced loads).
// Phase 2: each output element = wx1*G[c][x0] + wx0*G[c][x1] (2 LDS + 2 FMA).
__global__ void __launch_bounds__(256)
roirotate_kernel(const float* __restrict__ image,
                 const float* __restrict__ boxes,
                 float* __restrict__ out,
                 int max_w, int mask_mode)
{
    __shared__ float G[CN][NXMAX];

    const int blk = blockIdx.x;           // 0 .. BN*JN*HT-1
    const int bj  = blk >> 3;             // box index
    const int i   = blk & 7;              // output row
    const int b   = bj >> 6;              // JN = 64

    const float* bx = boxes + bj * 5;
    const float l   = bx[0];
    const float t   = bx[1];
    const float r   = bx[2];
    const float btm = bx[3];

    const float bwf = r - l;
    const float bhf = btm - t;
    // widths = int32( (bw/bh) * 8 ) in float32 arithmetic — keep EXACT
    const int width = (int)(__fmul_rn(__fdiv_rn(bwf, bhf), 8.0f));
    const float each_w = bwf / (float)(width - 1);
    const float each_h = bhf * (1.0f / 7.0f);   // HEIGHT-1 = 7

    const int chw = HT * max_w;

    // ---- mask (row-0 block of each box writes it) ----
    if (i == 0) {
        if (mask_mode == 0) {
            float* maskp = out + BN * JN * CN * chw + bj * max_w;
            for (int k = threadIdx.x; k < max_w; k += blockDim.x)
                maskp[k] = (k < width) ? 1.0f : 0.0f;
        } else if (mask_mode == 1) {
            unsigned char* maskp =
                (unsigned char*)(out + BN * JN * CN * chw) + bj * max_w;
            for (int k = threadIdx.x; k < max_w; k += blockDim.x)
                maskp[k] = (k < width) ? (unsigned char)1 : (unsigned char)0;
        }
    }

    // ---- y interpolation setup for this row ----
    const float y = (float)i * each_h + t;
    const float fy = floorf(y);
    const int y0 = min(max((int)fy,     0), HIMG_ - 1);
    const int y1 = min(max((int)fy + 1, 0), HIMG_ - 1);
    const float wy0 = y - (float)y0;      // weight for y1 row
    const float wy1 = (float)y1 - y;      // weight for y0 row

    // x-range covered by this box (+margin for float rounding at the right edge)
    const int xs = min(max((int)floorf(l), 0), WIMG_ - 1);
    const int xe = min((int)floorf(r) + 2, WIMG_ - 1);
    const int nx = xe - xs + 1;           // <= 204 <= NXMAX

    // ---- phase 1: blend two image rows into smem, all CN channels ----
    {
        const int x = threadIdx.x;
        if (x < nx) {
            const float* p0 = image + b * CN * HW + y0 * WIMG_ + xs + x;
            const float* p1 = image + b * CN * HW + y1 * WIMG_ + xs + x;
            #pragma unroll 4
            for (int c = 0; c < CN; c++) {
                G[c][x] = wy1 * __ldg(p0) + wy0 * __ldg(p1);
                p0 += HW;
                p1 += HW;
            }
        }
    }
    __syncthreads();

    // ---- phase 2: outputs for this row, all CN channels ----
    float* outrow = out + bj * CN * chw + i * max_w;    // + c*chw + k

    for (int k = threadIdx.x; k < max_w; k += blockDim.x) {
        float* o = outrow + k;
        if (k < width) {
            const float x = (float)k * each_w + l;
            const float fx = floorf(x);
            const int x0 = min(max((int)fx, 0), WIMG_ - 1);
            const int x1 = min(x0 + 1, WIMG_ - 1);
            const float wx0 = x - (float)x0;    // weight for x1 side
            const float wx1 = (float)x1 - x;    // weight for x0 side
            const int ix0 = min(max(x0 - xs, 0), nx - 1);
            const int ix1 = min(max(x1 - xs, 0), nx - 1);
            #pragma unroll 4
            for (int c = 0; c < CN; c++) {
                *o = wx1 * G[c][ix0] + wx0 * G[c][ix1];
                o += chw;
            }
        } else {
            #pragma unroll 8
            for (int c = 0; c < CN; c++) { *o = 0.0f; o += chw; }
        }
    }
}

extern "C" void kernel_launch(void* const* d_in, const int* in_sizes, int n_in,
                              void* d_out, int out_size)
{
    const float* image = (const float*)d_in[0];
    const float* boxes = (const float*)d_in[1];
    float* out = (float*)d_out;

    // Derive max_w from out_size (host-side, no sync needed).
    const long long per_res = (long long)BN * JN * CN * HT;     // 131072
    const long long per_fmask = per_res + (long long)BN * JN;   // 131584 (float mask)
    const long long per_u8 = per_res + (long long)BN * JN / 4;  // 131200 (u8 mask)

    int max_w, mask_mode;
    long long osz = (long long)out_size;
    if (osz % per_fmask == 0) {
        max_w = (int)(osz / per_fmask);
        mask_mode = 0;
    } else if (osz % per_u8 == 0) {
        max_w = (int)(osz / per_u8);
        mask_mode = 1;
    } else if (osz % per_res == 0) {
        max_w = (int)(osz / per_res);
        mask_mode = 2;
    } else {
        max_w = (int)(osz / per_fmask);
        mask_mode = 0;
    }

    dim3 grid(BN * JN * HT);
    roirotate_kernel<<<grid, 256>>>(image, boxes, out, max_w, mask_mode);
}

// round 16
// speedup vs baseline: 1.3268x; 1.3268x over previous
#include <cuda_runtime.h>

#define BN 8
#define JN 64
#define CN 32
#define CG 8               // channels per block group (grid.z = CN/CG = 4)
#define HT 8
#define HIMG_ 256
#define WIMG_ 256
#define HW (HIMG_*WIMG_)

// mask_mode: 0 = float mask after res, 1 = uint8 mask packed after res, 2 = no mask
__global__ void roirotate_kernel(const float* __restrict__ image,
                                 const float* __restrict__ boxes,
                                 float* __restrict__ out,
                                 int max_w, float inv_w, int mask_mode)
{
    __shared__ float s_l, s_t, s_ew, s_eh;
    __shared__ int   s_width;

    const int bj = blockIdx.y;               // 0 .. B*J-1
    const int b  = bj >> 6;                  // JN = 64
    const int c0 = blockIdx.z * CG;

    // ---- box params: once per block ----
    if (threadIdx.x == 0) {
        const float* bx = boxes + bj * 5;
        float l   = bx[0];
        float t   = bx[1];
        float bw  = bx[2] - l;
        float bh  = bx[3] - t;
        // widths = int32( (bw/bh) * 8 ) in float32 arithmetic — keep EXACT
        int width = (int)(__fmul_rn(__fdiv_rn(bw, bh), 8.0f));
        s_l = l;
        s_t = t;
        s_ew = bw / (float)(width - 1);
        s_eh = bh * (1.0f / 7.0f);            // HEIGHT-1 = 7
        s_width = width;
    }
    __syncthreads();

    const float l      = s_l;
    const float t      = s_t;
    const float each_w = s_ew;
    const float each_h = s_eh;
    const int   width  = s_width;

    const int chw = HT * max_w;               // per-channel output stride
    const float* imgb = image + (b * CN + c0) * HW;
    float* outb = out + (bj * CN + c0) * chw;

    // ---- mask (only one slice of blocks writes it) ----
    if (blockIdx.x == 0 && blockIdx.z == 0) {
        if (mask_mode == 0) {
            float* maskp = out + BN * JN * CN * chw + bj * max_w;
            for (int k = threadIdx.x; k < max_w; k += blockDim.x)
                maskp[k] = (k < width) ? 1.0f : 0.0f;
        } else if (mask_mode == 1) {
            unsigned char* maskp =
                (unsigned char*)(out + BN * JN * CN * chw) + bj * max_w;
            for (int k = threadIdx.x; k < max_w; k += blockDim.x)
                maskp[k] = (k < width) ? (unsigned char)1 : (unsigned char)0;
        }
    }

    const int idx = blockIdx.x * blockDim.x + threadIdx.x;   // over HT*max_w
    if (idx >= chw) return;

    // i = idx / max_w, k = idx % max_w via float reciprocal + exact fixup
    int i = (int)((float)idx * inv_w);
    int k = idx - i * max_w;
    if (k < 0)           { i--; k += max_w; }
    else if (k >= max_w) { i++; k -= max_w; }

    float* op = outb + idx;                   // == outb + i*max_w + k

    if (k >= width) {
        // masked region -> zeros (buffer poisoned, must write); coalesced per warp
        float* o = op;
        #pragma unroll
        for (int c = 0; c < CG; c++) { *o = 0.0f; o += chw; }
        return;
    }

    float x = (float)k * each_w + l;
    float y = (float)i * each_h + t;

    float fx = floorf(x), fy = floorf(y);
    int x0 = min(max((int)fx,     0), WIMG_ - 1);
    int x1 = min(max((int)fx + 1, 0), WIMG_ - 1);
    int y0 = min(max((int)fy,     0), HIMG_ - 1);
    int y1 = min(max((int)fy + 1, 0), HIMG_ - 1);

    float wx0 = x - (float)x0;     // weight for x1 side
    float wx1 = (float)x1 - x;     // weight for x0 side
    float wy0 = y - (float)y0;
    float wy1 = (float)y1 - y;

    float wa = wx1 * wy1;   // (y0,x0)
    float wb = wx1 * wy0;   // (y1,x0)
    float wc = wx0 * wy1;   // (y0,x1)
    float wd = wx0 * wy0;   // (y1,x1)

    const int o00 = y0 * WIMG_ + x0;
    const int o01 = y0 * WIMG_ + x1;
    const int o10 = y1 * WIMG_ + x0;
    const int o11 = y1 * WIMG_ + x1;

    const float* ip = imgb;
    float* o = op;
    #pragma unroll
    for (int c = 0; c < CG; c++) {
        float v = __ldg(ip + o00) * wa
                + __ldg(ip + o10) * wb
                + __ldg(ip + o01) * wc
                + __ldg(ip + o11) * wd;
        *o = v;
        ip += HW;
        o  += chw;
    }
}

extern "C" void kernel_launch(void* const* d_in, const int* in_sizes, int n_in,
                              void* d_out, int out_size)
{
    const float* image = (const float*)d_in[0];
    const float* boxes = (const float*)d_in[1];
    float* out = (float*)d_out;

    // Derive max_w from out_size (host-side, no sync needed).
    const long long per_res = (long long)BN * JN * CN * HT;     // 131072
    const long long per_fmask = per_res + (long long)BN * JN;   // 131584 (float mask)
    const long long per_u8 = per_res + (long long)BN * JN / 4;  // 131200 (u8 mask)

    int max_w, mask_mode;
    long long osz = (long long)out_size;
    if (osz % per_fmask == 0) {
        max_w = (int)(osz / per_fmask);
        mask_mode = 0;
    } else if (osz % per_u8 == 0) {
        max_w = (int)(osz / per_u8);
        mask_mode = 1;
    } else if (osz % per_res == 0) {
        max_w = (int)(osz / per_res);
        mask_mode = 2;
    } else {
        max_w = (int)(osz / per_fmask);
        mask_mode = 0;
    }

    const int block = 256;
    int slices = (HT * max_w + block - 1) / block;
    dim3 grid(slices, BN * JN, CN / CG);
    float inv_w = 1.0f / (float)max_w;
    roirotate_kernel<<<grid, block>>>(image, boxes, out, max_w, inv_w, mask_mode);
}

// round 17
// speedup vs baseline: 1.3934x; 1.0502x over previous
#include <cuda_runtime.h>

#define BN 8
#define JN 64
#define CN 32
#define CG 8               // channels per block group (grid.z = CN/CG = 4)
#define HT 8
#define HIMG_ 256
#define WIMG_ 256
#define HW (HIMG_*WIMG_)

// mask_mode: 0 = float mask after res, 1 = uint8 mask packed after res, 2 = no mask
__global__ void roirotate_kernel(const float* __restrict__ image,
                                 const float* __restrict__ boxes,
                                 float* __restrict__ out,
                                 int max_w, float inv_w, int mask_mode)
{
    __shared__ float s_l, s_t, s_ew, s_eh;
    __shared__ int   s_width;

    const int bj = blockIdx.y;               // 0 .. B*J-1
    const int b  = bj >> 6;                  // JN = 64
    const int c0 = blockIdx.z * CG;

    // ---- box params: once per block ----
    if (threadIdx.x == 0) {
        const float* bx = boxes + bj * 5;
        float l   = bx[0];
        float t   = bx[1];
        float bw  = bx[2] - l;
        float bh  = bx[3] - t;
        // widths = int32( (bw/bh) * 8 ) in float32 arithmetic — keep EXACT
        int width = (int)(__fmul_rn(__fdiv_rn(bw, bh), 8.0f));
        s_l = l;
        s_t = t;
        s_ew = bw / (float)(width - 1);
        s_eh = bh * (1.0f / 7.0f);            // HEIGHT-1 = 7
        s_width = width;
    }
    __syncthreads();

    const float l      = s_l;
    const float t      = s_t;
    const float each_w = s_ew;
    const float each_h = s_eh;
    const int   width  = s_width;

    const int chw = HT * max_w;               // per-channel output stride
    const float* imgb = image + (b * CN + c0) * HW;
    float* outb = out + (bj * CN + c0) * chw;

    // ---- mask (only one slice of blocks writes it) ----
    if (blockIdx.x == 0 && blockIdx.z == 0) {
        if (mask_mode == 0) {
            float* maskp = out + BN * JN * CN * chw + bj * max_w;
            for (int k = threadIdx.x; k < max_w; k += blockDim.x)
                __stcs(maskp + k, (k < width) ? 1.0f : 0.0f);
        } else if (mask_mode == 1) {
            unsigned char* maskp =
                (unsigned char*)(out + BN * JN * CN * chw) + bj * max_w;
            for (int k = threadIdx.x; k < max_w; k += blockDim.x)
                maskp[k] = (k < width) ? (unsigned char)1 : (unsigned char)0;
        }
    }

    const int idx = blockIdx.x * blockDim.x + threadIdx.x;   // over HT*max_w
    if (idx >= chw) return;

    // i = idx / max_w, k = idx % max_w via float reciprocal + exact fixup
    int i = (int)((float)idx * inv_w);
    int k = idx - i * max_w;
    if (k < 0)           { i--; k += max_w; }
    else if (k >= max_w) { i++; k -= max_w; }

    float* op = outb + idx;                   // == outb + i*max_w + k

    if (k >= width) {
        // masked region -> zeros; evict-first so the stream doesn't pollute L2
        float* o = op;
        #pragma unroll
        for (int c = 0; c < CG; c++) { __stcs(o, 0.0f); o += chw; }
        return;
    }

    float x = (float)k * each_w + l;
    float y = (float)i * each_h + t;

    float fx = floorf(x), fy = floorf(y);
    int x0 = min(max((int)fx,     0), WIMG_ - 1);
    int x1 = min(max((int)fx + 1, 0), WIMG_ - 1);
    int y0 = min(max((int)fy,     0), HIMG_ - 1);
    int y1 = min(max((int)fy + 1, 0), HIMG_ - 1);

    float wx0 = x - (float)x0;     // weight for x1 side
    float wx1 = (float)x1 - x;     // weight for x0 side
    float wy0 = y - (float)y0;
    float wy1 = (float)y1 - y;

    float wa = wx1 * wy1;   // (y0,x0)
    float wb = wx1 * wy0;   // (y1,x0)
    float wc = wx0 * wy1;   // (y0,x1)
    float wd = wx0 * wy0;   // (y1,x1)

    const int o00 = y0 * WIMG_ + x0;
    const int o01 = y0 * WIMG_ + x1;
    const int o10 = y1 * WIMG_ + x0;
    const int o11 = y1 * WIMG_ + x1;

    const float* ip = imgb;
    float* o = op;
    #pragma unroll
    for (int c = 0; c < CG; c++) {
        float v = __ldg(ip + o00) * wa
                + __ldg(ip + o10) * wb
                + __ldg(ip + o01) * wc
                + __ldg(ip + o11) * wd;
        __stcs(o, v);                         // evict-first: keep image in L2
        ip += HW;
        o  += chw;
    }
}

extern "C" void kernel_launch(void* const* d_in, const int* in_sizes, int n_in,
                              void* d_out, int out_size)
{
    const float* image = (const float*)d_in[0];
    const float* boxes = (const float*)d_in[1];
    float* out = (float*)d_out;

    // Derive max_w from out_size (host-side, no sync needed).
    const long long per_res = (long long)BN * JN * CN * HT;     // 131072
    const long long per_fmask = per_res + (long long)BN * JN;   // 131584 (float mask)
    const long long per_u8 = per_res + (long long)BN * JN / 4;  // 131200 (u8 mask)

    int max_w, mask_mode;
    long long osz = (long long)out_size;
    if (osz % per_fmask == 0) {
        max_w = (int)(osz / per_fmask);
        mask_mode = 0;
    } else if (osz % per_u8 == 0) {
        max_w = (int)(osz / per_u8);
        mask_mode = 1;
    } else if (osz % per_res == 0) {
        max_w = (int)(osz / per_res);
        mask_mode = 2;
    } else {
        max_w = (int)(osz / per_fmask);
        mask_mode = 0;
    }

    const int block = 256;
    int slices = (HT * max_w + block - 1) / block;
    dim3 grid(slices, BN * JN, CN / CG);
    float inv_w = 1.0f / (float)max_w;
    roirotate_kernel<<<grid, block>>>(image, boxes, out, max_w, inv_w, mask_mode);
}